// round 5
// baseline (speedup 1.0000x reference)
#include <cuda_runtime.h>
#include <cstdint>
#include <cstddef>

#define Dv 100
typedef unsigned long long ull;

__device__ __forceinline__ void ffma2(ull &d, ull a, ull b) {
    asm("fma.rn.f32x2 %0, %1, %2, %0;" : "+l"(d) : "l"(a), "l"(b));
}
__device__ __forceinline__ ull dup2(float v) {
    ull r; asm("mov.b64 %0, {%1, %1};" : "=l"(r) : "f"(v)); return r;
}
__device__ __forceinline__ ull pack2(float lo, float hi) {
    ull r; asm("mov.b64 %0, {%1, %2};" : "=l"(r) : "f"(lo), "f"(hi)); return r;
}
__device__ __forceinline__ float2 unpack2(ull v) {
    float2 r; asm("mov.b64 {%0, %1}, %2;" : "=f"(r.x), "=f"(r.y) : "l"(v)); return r;
}
__device__ __forceinline__ void lds_v2u64(ull &a, ull &b, const void* p) {
    unsigned sa = (unsigned)__cvta_generic_to_shared(p);
    asm("ld.shared.v2.u64 {%0, %1}, [%2];" : "=l"(a), "=l"(b) : "r"(sa));
}
// (mz >= 0) ? 0 : x  — with mz = nla - n = -(la+noise): gives (la+noise>0) ? x : 0
__device__ __forceinline__ float slct0(float x, float mz) {
    float r;
    asm("slct.f32.f32 %0, %1, %2, %3;" : "=f"(r) : "f"(0.0f), "f"(x), "f"(mz));
    return r;
}
__device__ __forceinline__ void cp16(unsigned dst, const void* src) {
    asm volatile("cp.async.cg.shared.global [%0], [%1], 16;" :: "r"(dst), "l"(src) : "memory");
}
__device__ __forceinline__ float lrelu(float a) { return fmaxf(a, 0.01f * a); }

struct Smem {
    ull   w0p[Dv][2][8][4];    // [j][ih][tt][q]: i-pair (i=ih*8+2q,+1) of W0[t][i][j]  51200B
    float xs[64][104];         // [bb][j]                                               26624B
    float nlas[Dv][8];         // -log_alpha[j][t]; +3e38 if j==t or t>=100              3200B
    float nstg[3][4][64][8];   // noise ring [stage][jj][rowidx][tt]                    24576B
    ull   w1p[8][2][16][4];    // [tt][ih][jj][q]: i'-pair of W1[t][i'][jj]              8192B
    ull   b0p[8][2][4];        //                                                         512B
    ull   b1p[8][2][4];        //                                                         512B
    ull   w2p[8][2][2][4];     // [tt][ih][p][q]                                         1024B
    float b2s[8][2];           //                                                          64B
};                             // total 115904B -> 2 blocks/SM

#define NOISE_LIMIT 40959996L  // last 16B-aligned start inside noise[]

__global__ __launch_bounds__(256, 2)
void fused_nri_kernel(const float* __restrict__ x,
                      const float* __restrict__ la_g,
                      const float* __restrict__ noise,
                      const float* __restrict__ W0,
                      const float* __restrict__ b0g,
                      const float* __restrict__ W1,
                      const float* __restrict__ b1g,
                      const float* __restrict__ W2,
                      const float* __restrict__ b2g,
                      float* __restrict__ out)
{
    extern __shared__ char smem_raw[];
    Smem& S = *reinterpret_cast<Smem*>(smem_raw);
    const int tid = threadIdx.x;
    const int t_tile = blockIdx.x >> 6;
    const int b_blk  = blockIdx.x & 63;
    const int t0 = t_tile * 8;
    const int bbase = b_blk * 64;

    float* nstg_f = &S.nstg[0][0][0][0];
    const unsigned nstg_u32 = (unsigned)__cvta_generic_to_shared(nstg_f);

    // issue one 4-j noise chunk into the ring at byte offset offB
    #define ISSUE_CHUNK(chunkIdx, offB) do {                                          \
        int _jb = (chunkIdx) * 4;                                                     \
        _Pragma("unroll")                                                             \
        for (int _u = 0; _u < 2; _u++) {                                              \
            int _o = tid + _u * 256;                                                  \
            int _h = _o & 1, _row = (_o >> 1) & 63, _jj = _o >> 7;                    \
            long _src = (long)(bbase + _row) * 10000 + (long)((_jb + _jj) * 100 + t0 + _h * 4); \
            if (_src > NOISE_LIMIT) _src = NOISE_LIMIT;                               \
            int _ri = (_row >> 2) | ((_row & 3) << 4);                                \
            unsigned _dst = nstg_u32 + (unsigned)(offB)                               \
                          + (unsigned)((((_jj << 6) + _ri) * 8 + _h * 4) * 4);        \
            cp16(_dst, noise + _src);                                                 \
        }                                                                             \
    } while (0)

    // ---- prologue: start chunks 0 and 1 before doing anything else ----
    ISSUE_CHUNK(0, 0);
    asm volatile("cp.async.commit_group;" ::: "memory");
    ISSUE_CHUNK(1, 8192);
    asm volatile("cp.async.commit_group;" ::: "memory");

    // ---- stage W0 tile as i-pairs [j][ih][tt][q] (coalesced over j) ----
    {
        float* w0f = reinterpret_cast<float*>(S.w0p);
        for (int e = tid; e < 8 * 16 * Dv; e += 256) {
            int tt = e / (16 * Dv);
            int r  = e - tt * 16 * Dv;
            int i  = r / Dv;
            int j  = r - i * Dv;
            int t  = t0 + tt;
            float v = (t < Dv) ? W0[(t * 16 + i) * Dv + j] : 0.f;
            int idx = ((((j * 2 + (i >> 3)) * 8 + tt) * 4 + ((i >> 1) & 3)) * 2) + (i & 1);
            w0f[idx] = v;
        }
    }
    // ---- x tile [bb][j] ----
    for (int e = tid; e < 64 * Dv; e += 256) {
        int bb = e / Dv;
        int j  = e - bb * Dv;
        S.xs[bb][j] = x[(bbase + bb) * Dv + j];
    }
    // ---- negated log_alpha with adj + guard folded in ----
    for (int e = tid; e < 8 * Dv; e += 256) {
        int j = e >> 3, tt = e & 7, t = t0 + tt;
        float v = 3e38f;
        if (t < Dv && j != t) v = -la_g[j * Dv + t];
        S.nlas[j][tt] = v;
    }
    // ---- W1 as i'-pairs [tt][ih][jj][q] ----
    {
        float* w1f = reinterpret_cast<float*>(S.w1p);
        for (int e = tid; e < 8 * 16 * 16; e += 256) {
            int tt = e >> 8, r = e & 255, i = r >> 4, jj = r & 15, t = t0 + tt;
            float v = (t < Dv) ? W1[(t * 16 + i) * 16 + jj] : 0.f;
            int idx = ((((tt * 2 + (i >> 3)) * 16 + jj) * 4 + ((i >> 1) & 3)) * 2) + (i & 1);
            w1f[idx] = v;
        }
    }
    // ---- biases, W2 ----
    if (tid < 128) {
        int tt = tid >> 4, i = tid & 15, t = t0 + tt;
        int idx = (((tt * 2 + (i >> 3)) * 4 + ((i >> 1) & 3)) * 2) + (i & 1);
        reinterpret_cast<float*>(S.b0p)[idx] = (t < Dv) ? b0g[t * 16 + i] : 0.f;
        reinterpret_cast<float*>(S.b1p)[idx] = (t < Dv) ? b1g[t * 16 + i] : 0.f;
    }
    {
        float* w2f = reinterpret_cast<float*>(S.w2p);
        for (int e = tid; e < 8 * 2 * 16; e += 256) {
            int tt = e >> 5, r = e & 31, p = r >> 4, i = r & 15, t = t0 + tt;
            int idx = ((((tt * 2 + (i >> 3)) * 2 + p) * 4 + ((i >> 1) & 3)) * 2) + (i & 1);
            w2f[idx] = (t < Dv) ? W2[(t * 2 + p) * 16 + i] : 0.f;
        }
    }
    if (tid < 16) {
        int tt = tid >> 1, p = tid & 1, t = t0 + tt;
        S.b2s[tt][p] = (t < Dv) ? b2g[t * 2 + p] : 0.f;
    }
    __syncthreads();

    const int lane = tid & 31;
    const int warp = tid >> 5;
    const int tt   = lane & 7;          // 8 consecutive t
    const int ih   = (lane >> 3) & 1;   // i half
    const int bs   = lane >> 4;         // row-group slot
    const int t    = t0 + tt;
    const int w2b  = warp * 2 + bs;
    const int rowb = w2b * 4;           // 4 batch rows per thread

    ull acc[4][4];
    #pragma unroll
    for (int k = 0; k < 4; k++)
        #pragma unroll
        for (int q = 0; q < 4; q++) acc[k][q] = 0ull;

    unsigned cons_off = 0;      // stage byte offset being consumed
    unsigned fill_off = 16384;  // stage byte offset to fill next (chunk 2 -> stage 2)

    // ---- main loop: 25 chunks of 4 j ----
    for (int c = 0; c < 25; c++) {
        // chunk c ready once <=1 groups outstanding ({c, c+1} before this)
        asm volatile("cp.async.wait_group 1;" ::: "memory");
        __syncthreads();

        if (c + 2 < 25) ISSUE_CHUNK(c + 2, fill_off);
        asm volatile("cp.async.commit_group;" ::: "memory");
        fill_off = (fill_off == 16384u) ? 0u : fill_off + 8192u;

        // x for the 4 rows, 4 j of this chunk
        float4 xr[4];
        #pragma unroll
        for (int k = 0; k < 4; k++)
            xr[k] = *reinterpret_cast<const float4*>(&S.xs[rowb + k][4 * c]);

        const float* np = nstg_f + (cons_off >> 2) + w2b * 8 + tt;

        #pragma unroll
        for (int jj = 0; jj < 4; jj++) {
            const int j = 4 * c + jj;
            ull w[4];
            const ull* w0u = &S.w0p[j][ih][tt][0];
            lds_v2u64(w[0], w[1], w0u);
            lds_v2u64(w[2], w[3], w0u + 2);
            const float nla = S.nlas[j][tt];
            const float xj[4] = {
                jj == 0 ? xr[0].x : jj == 1 ? xr[0].y : jj == 2 ? xr[0].z : xr[0].w,
                jj == 0 ? xr[1].x : jj == 1 ? xr[1].y : jj == 2 ? xr[1].z : xr[1].w,
                jj == 0 ? xr[2].x : jj == 1 ? xr[2].y : jj == 2 ? xr[2].z : xr[2].w,
                jj == 0 ? xr[3].x : jj == 1 ? xr[3].y : jj == 2 ? xr[3].z : xr[3].w };
            #pragma unroll
            for (int k = 0; k < 4; k++) {
                float n  = np[jj * 512 + k * 128];
                float mz = nla - n;
                ull xp = dup2(slct0(xj[k], mz));
                ffma2(acc[k][0], w[0], xp);
                ffma2(acc[k][1], w[1], xp);
                ffma2(acc[k][2], w[2], xp);
                ffma2(acc[k][3], w[3], xp);
            }
        }
        cons_off = (cons_off == 16384u) ? 0u : cons_off + 8192u;
    }
    asm volatile("cp.async.wait_group 0;" ::: "memory");

    // ---- epilogue: layers 1 & 2, i-halves recombined via shfl_xor(8) ----
    ull b0r[4], b1r[4], w2r0[4], w2r1[4];
    #pragma unroll
    for (int q = 0; q < 4; q++) {
        b0r[q]  = S.b0p[tt][ih][q];
        b1r[q]  = S.b1p[tt][ih][q];
        w2r0[q] = S.w2p[tt][ih][0][q];
        w2r1[q] = S.w2p[tt][ih][1][q];
    }

    #pragma unroll
    for (int k = 0; k < 4; k++) {
        float hfull[16];
        ull hp[4];
        #pragma unroll
        for (int q = 0; q < 4; q++) {
            float2 a = unpack2(acc[k][q]);
            float2 b = unpack2(b0r[q]);
            float a0 = lrelu(a.x + b.x);
            float a1 = lrelu(a.y + b.y);
            hfull[ih * 8 + 2 * q]     = a0;
            hfull[ih * 8 + 2 * q + 1] = a1;
            hp[q] = pack2(a0, a1);
        }
        #pragma unroll
        for (int q = 0; q < 4; q++) {
            ull ho = __shfl_xor_sync(0xffffffffu, hp[q], 8);
            float2 v = unpack2(ho);
            hfull[(1 - ih) * 8 + 2 * q]     = v.x;
            hfull[(1 - ih) * 8 + 2 * q + 1] = v.y;
        }
        ull a2[4] = { b1r[0], b1r[1], b1r[2], b1r[3] };
        #pragma unroll
        for (int jj = 0; jj < 16; jj++) {
            ull wv0, wv1, wv2, wv3;
            const ull* w1u = &S.w1p[tt][ih][jj][0];
            lds_v2u64(wv0, wv1, w1u);
            lds_v2u64(wv2, wv3, w1u + 2);
            ull hv = dup2(hfull[jj]);
            ffma2(a2[0], wv0, hv);
            ffma2(a2[1], wv1, hv);
            ffma2(a2[2], wv2, hv);
            ffma2(a2[3], wv3, hv);
        }
        ull o0p = 0ull, o1p = 0ull;
        #pragma unroll
        for (int q = 0; q < 4; q++) {
            float2 g = unpack2(a2[q]);
            ull gp = pack2(lrelu(g.x), lrelu(g.y));
            ffma2(o0p, w2r0[q], gp);
            ffma2(o1p, w2r1[q], gp);
        }
        float2 s0 = unpack2(o0p), s1 = unpack2(o1p);
        float o0 = s0.x + s0.y;
        float o1 = s1.x + s1.y;
        o0 += __shfl_xor_sync(0xffffffffu, o0, 8);
        o1 += __shfl_xor_sync(0xffffffffu, o1, 8);
        if (ih == 0 && t < Dv) {
            int b = bbase + rowb + k;
            reinterpret_cast<float2*>(out)[b * Dv + t] =
                make_float2(o0 + S.b2s[tt][0], o1 + S.b2s[tt][1]);
        }
    }
    #undef ISSUE_CHUNK
}

extern "C" void kernel_launch(void* const* d_in, const int* in_sizes, int n_in,
                              void* d_out, int out_size)
{
    const float* x   = (const float*)d_in[0];
    const float* la  = (const float*)d_in[1];
    const float* nz  = (const float*)d_in[2];
    const float* W0  = (const float*)d_in[3];
    const float* b0  = (const float*)d_in[4];
    const float* W1  = (const float*)d_in[5];
    const float* b1  = (const float*)d_in[6];
    const float* W2  = (const float*)d_in[7];
    const float* b2  = (const float*)d_in[8];
    float* out = (float*)d_out;

    cudaFuncSetAttribute(fused_nri_kernel,
                         cudaFuncAttributeMaxDynamicSharedMemorySize,
                         (int)sizeof(Smem));
    fused_nri_kernel<<<13 * 64, 256, sizeof(Smem)>>>(
        x, la, nz, W0, b0, W1, b1, W2, b2, out);
}

// round 7
// speedup vs baseline: 2.0466x; 2.0466x over previous
#include <cuda_runtime.h>
#include <cstdint>
#include <cstddef>

#define Dv 100
typedef unsigned long long ull;

__device__ __forceinline__ void ffma2(ull &d, ull a, ull b) {
    asm("fma.rn.f32x2 %0, %1, %2, %0;" : "+l"(d) : "l"(a), "l"(b));
}
__device__ __forceinline__ ull dup2(float v) {
    ull r; asm("mov.b64 %0, {%1, %1};" : "=l"(r) : "f"(v)); return r;
}
__device__ __forceinline__ ull pack2(float lo, float hi) {
    ull r; asm("mov.b64 %0, {%1, %2};" : "=l"(r) : "f"(lo), "f"(hi)); return r;
}
__device__ __forceinline__ float2 unpack2(ull v) {
    float2 r; asm("mov.b64 {%0, %1}, %2;" : "=f"(r.x), "=f"(r.y) : "l"(v)); return r;
}
__device__ __forceinline__ void lds_v2u64(ull &a, ull &b, const void* p) {
    unsigned sa = (unsigned)__cvta_generic_to_shared(p);
    asm("ld.shared.v2.u64 {%0, %1}, [%2];" : "=l"(a), "=l"(b) : "r"(sa));
}
// (mz >= 0) ? 0 : x  — with mz = nla - n = -(la+noise): gives (la+noise>0) ? x : 0
__device__ __forceinline__ float slct0(float x, float mz) {
    float r;
    asm("slct.f32.f32 %0, %1, %2, %3;" : "=f"(r) : "f"(0.0f), "f"(x), "f"(mz));
    return r;
}
__device__ __forceinline__ void cp16(unsigned dst, const void* src) {
    asm volatile("cp.async.cg.shared.global [%0], [%1], 16;" :: "r"(dst), "l"(src) : "memory");
}
__device__ __forceinline__ float lrelu(float a) { return fmaxf(a, 0.01f * a); }

struct Smem {
    float4 w0s[Dv][4][8];     // [j][i4][tt] : (W0[t0+tt][4*i4+c][j])        51200B
    float  xs[64][Dv];        // [bb][j]                                     25600B
    float  nlas[Dv][8];       // -log_alpha[j][t]; +3e38 if j==t or t>=100    3200B
    float  nring[8][3][256];  // per-warp noise ring [warp][stage][jj*64+ri*8+tt] 24576B
    float  w1s[16][8][8][2];  // [jj][i2][tt][half] : W1[t][2*i2+half][jj]    8192B
};                            // total 112768B -> 2 blocks/SM

#define NOISE_LIMIT 40959996L   // last valid 16B-aligned element start

__global__ __launch_bounds__(256, 2)
void fused_nri_kernel(const float* __restrict__ x,
                      const float* __restrict__ la_g,
                      const float* __restrict__ noise,
                      const float* __restrict__ W0,
                      const float* __restrict__ b0g,
                      const float* __restrict__ W1,
                      const float* __restrict__ b1g,
                      const float* __restrict__ W2,
                      const float* __restrict__ b2g,
                      float* __restrict__ out)
{
    extern __shared__ char smem_raw[];
    Smem& S = *reinterpret_cast<Smem*>(smem_raw);
    const int tid = threadIdx.x;
    const int lane = tid & 31;
    const int warp = tid >> 5;
    const int t_tile = blockIdx.x >> 6;
    const int b_blk  = blockIdx.x & 63;
    const int t0 = t_tile * 8;
    const int bbase = b_blk * 64;

    // ---- per-warp noise producer setup: 2 cp16 per lane per 4-j chunk ----
    long nbase[2]; unsigned ndst[2];
    #pragma unroll
    for (int u = 0; u < 2; u++) {
        int o = lane + u * 32;
        int h = o & 1, row = (o >> 1) & 7, jjp = (o >> 4) & 3;
        int ri = ((row & 1) << 2) | (row >> 1);
        nbase[u] = (long)(bbase + warp * 8 + row) * 10000 + (long)(jjp * 100 + t0 + h * 4);
        ndst[u] = (unsigned)((jjp * 64 + ri * 8 + h * 4) * 4);
    }
    const unsigned rb = (unsigned)__cvta_generic_to_shared(&S.nring[warp][0][0]);

    #define ISSUE(c, st) do {                                            \
        long _off = (long)(c) * 400;                                     \
        _Pragma("unroll")                                                \
        for (int _u = 0; _u < 2; _u++) {                                 \
            long _s = nbase[_u] + _off;                                  \
            if (_s > NOISE_LIMIT) _s = NOISE_LIMIT;                      \
            cp16(rb + (unsigned)(st) * 1024u + ndst[_u], noise + _s);    \
        }                                                                \
    } while (0)

    // prologue: 3 chunks in flight before anything else
    ISSUE(0, 0); asm volatile("cp.async.commit_group;" ::: "memory");
    ISSUE(1, 1); asm volatile("cp.async.commit_group;" ::: "memory");
    ISSUE(2, 2); asm volatile("cp.async.commit_group;" ::: "memory");

    // ---- stage W0 tile (coalesced over j) ----
    for (int e = tid; e < 8 * 16 * Dv; e += 256) {
        int tt = e / (16 * Dv);
        int r  = e - tt * 16 * Dv;
        int i  = r / Dv;
        int j  = r - i * Dv;
        int t  = t0 + tt;
        float v = (t < Dv) ? W0[(t * 16 + i) * Dv + j] : 0.f;
        reinterpret_cast<float*>(&S.w0s[j][i >> 2][tt])[i & 3] = v;
    }
    // ---- x tile [bb][j] ----
    for (int e = tid; e < 64 * Dv; e += 256) {
        int bb = e / Dv;
        int j  = e - bb * Dv;
        S.xs[bb][j] = x[(bbase + bb) * Dv + j];
    }
    // ---- negated log_alpha with adj + tile guard folded in ----
    for (int e = tid; e < 8 * Dv; e += 256) {
        int j = e >> 3, tt = e & 7, t = t0 + tt;
        float v = 3e38f;
        if (t < Dv && j != t) v = -la_g[j * Dv + t];
        S.nlas[j][tt] = v;
    }
    // ---- W1 as i-pairs ----
    for (int e = tid; e < 8 * 16 * 16; e += 256) {
        int tt = e >> 8, r = e & 255, i = r >> 4, jj = r & 15, t = t0 + tt;
        S.w1s[jj][i >> 1][tt][i & 1] = (t < Dv) ? W1[(t * 16 + i) * 16 + jj] : 0.f;
    }
    __syncthreads();

    const int tt  = lane & 7;       // 8 consecutive t per warp
    const int bbg = lane >> 3;      // 4 row-pair slots
    const int t   = t0 + tt;
    const int rowb = warp * 8 + bbg * 2;    // 2 batch rows per thread

    ull acc[2][8];
    #pragma unroll
    for (int k = 0; k < 2; k++)
        #pragma unroll
        for (int q = 0; q < 8; q++) acc[k][q] = 0ull;

    // ---- main loop: 25 chunks of 4 j, warp-private pipeline ----
    for (int c = 0; c < 25; c++) {
        asm volatile("cp.async.wait_group 2;" ::: "memory");
        __syncwarp();

        const int st = c % 3;
        const float* np = &S.nring[warp][st][0];

        float4 x0 = *reinterpret_cast<const float4*>(&S.xs[rowb][4 * c]);
        float4 x1 = *reinterpret_cast<const float4*>(&S.xs[rowb + 1][4 * c]);

        #pragma unroll
        for (int jj = 0; jj < 4; jj++) {
            const int j = 4 * c + jj;
            ull w[8];
            lds_v2u64(w[0], w[1], &S.w0s[j][0][tt]);
            lds_v2u64(w[2], w[3], &S.w0s[j][1][tt]);
            lds_v2u64(w[4], w[5], &S.w0s[j][2][tt]);
            lds_v2u64(w[6], w[7], &S.w0s[j][3][tt]);

            const float nla = S.nlas[j][tt];
            float n0 = np[jj * 64 + bbg * 8 + tt];
            float n1 = np[jj * 64 + (4 + bbg) * 8 + tt];
            float xj0 = jj == 0 ? x0.x : jj == 1 ? x0.y : jj == 2 ? x0.z : x0.w;
            float xj1 = jj == 0 ? x1.x : jj == 1 ? x1.y : jj == 2 ? x1.z : x1.w;

            ull xp0 = dup2(slct0(xj0, nla - n0));
            ull xp1 = dup2(slct0(xj1, nla - n1));

            #pragma unroll
            for (int q = 0; q < 8; q++) ffma2(acc[0][q], w[q], xp0);
            #pragma unroll
            for (int q = 0; q < 8; q++) ffma2(acc[1][q], w[q], xp1);
        }

        if (c + 3 < 25) ISSUE(c + 3, st);       // stage (c+3)%3 == c%3, just freed
        asm volatile("cp.async.commit_group;" ::: "memory");
    }
    #undef ISSUE

    // ---- epilogue: layers 1 & 2; b0/b1/W2/b2 straight from global (L2-hot) ----
    const int t_eff = (t < Dv) ? t : (Dv - 1);
    float b0a[16], b1a[16], w2a0[16], w2a1[16];
    {
        const float4* p0 = reinterpret_cast<const float4*>(b0g + t_eff * 16);
        const float4* p1 = reinterpret_cast<const float4*>(b1g + t_eff * 16);
        const float4* p2 = reinterpret_cast<const float4*>(W2 + t_eff * 32);
        #pragma unroll
        for (int q = 0; q < 4; q++) {
            float4 v0 = p0[q], v1 = p1[q], v2 = p2[q], v3 = p2[q + 4];
            b0a[4*q] = v0.x; b0a[4*q+1] = v0.y; b0a[4*q+2] = v0.z; b0a[4*q+3] = v0.w;
            b1a[4*q] = v1.x; b1a[4*q+1] = v1.y; b1a[4*q+2] = v1.z; b1a[4*q+3] = v1.w;
            w2a0[4*q] = v2.x; w2a0[4*q+1] = v2.y; w2a0[4*q+2] = v2.z; w2a0[4*q+3] = v2.w;
            w2a1[4*q] = v3.x; w2a1[4*q+1] = v3.y; w2a1[4*q+2] = v3.z; w2a1[4*q+3] = v3.w;
        }
    }
    float2 b2v = *reinterpret_cast<const float2*>(b2g + t_eff * 2);

    #pragma unroll
    for (int k = 0; k < 2; k++) {
        float h[16];
        #pragma unroll
        for (int q = 0; q < 8; q++) {
            float2 v = unpack2(acc[k][q]);
            h[2*q]   = lrelu(v.x + b0a[2*q]);
            h[2*q+1] = lrelu(v.y + b0a[2*q+1]);
        }
        ull a2[8];
        #pragma unroll
        for (int q = 0; q < 8; q++) a2[q] = pack2(b1a[2*q], b1a[2*q+1]);
        #pragma unroll
        for (int jj = 0; jj < 16; jj++) {
            ull hv = dup2(h[jj]);
            #pragma unroll
            for (int q = 0; q < 8; q++) {
                ull wv = *reinterpret_cast<const ull*>(&S.w1s[jj][q][tt][0]);
                ffma2(a2[q], wv, hv);
            }
        }
        ull o0p = 0ull, o1p = 0ull;
        #pragma unroll
        for (int q = 0; q < 8; q++) {
            float2 g = unpack2(a2[q]);
            ull gp = pack2(lrelu(g.x), lrelu(g.y));
            ffma2(o0p, pack2(w2a0[2*q], w2a0[2*q+1]), gp);
            ffma2(o1p, pack2(w2a1[2*q], w2a1[2*q+1]), gp);
        }
        float2 s0 = unpack2(o0p), s1 = unpack2(o1p);
        if (t < Dv) {
            int b = bbase + rowb + k;
            reinterpret_cast<float2*>(out)[b * Dv + t] =
                make_float2(s0.x + s0.y + b2v.x, s1.x + s1.y + b2v.y);
        }
    }
}

extern "C" void kernel_launch(void* const* d_in, const int* in_sizes, int n_in,
                              void* d_out, int out_size)
{
    const float* x   = (const float*)d_in[0];
    const float* la  = (const float*)d_in[1];
    const float* nz  = (const float*)d_in[2];
    const float* W0  = (const float*)d_in[3];
    const float* b0  = (const float*)d_in[4];
    const float* W1  = (const float*)d_in[5];
    const float* b1  = (const float*)d_in[6];
    const float* W2  = (const float*)d_in[7];
    const float* b2  = (const float*)d_in[8];
    float* out = (float*)d_out;

    cudaFuncSetAttribute(fused_nri_kernel,
                         cudaFuncAttributeMaxDynamicSharedMemorySize,
                         (int)sizeof(Smem));
    fused_nri_kernel<<<13 * 64, 256, sizeof(Smem)>>>(
        x, la, nz, W0, b0, W1, b1, W2, b2, out);
}